// round 11
// baseline (speedup 1.0000x reference)
#include <cuda_runtime.h>
#include <cuda_fp16.h>
#include <cstdint>

// ============================================================================
// out[m,n] = scale * sum_k x[m,k] * w[n,k]
//   M = 8192, K = 4096, N = 11008; x fp32, w int32 (int8-valued), scale fp32.
//
// Harness ptxas target is base sm_103 (no 'a'): tcgen05/TMEM are NOT available.
// Use portable compute_80 ISA: mma.sync m16n8k16 f16->f32, ldmatrix, cp.async.
//
//   1) prepack: w -> fp16 (exact), x -> fp16 (rel err ~3e-4 < 1e-3)
//   2) GEMM: 128x128 CTA tile, KC=32 chunks, 4-stage cp.async pipeline,
//      8 warps (4x2), warp tile 32x64, padded smem (stride 80B) -> conflict-free
//      ldmatrix.x4, fp32 accum, scale in epilogue.
// ============================================================================

static constexpr int M = 8192;
static constexpr int N = 11008;
static constexpr int K = 4096;
static constexpr int TM = 128;
static constexpr int TN = 128;
static constexpr int KC = 32;                 // K elems per pipeline chunk
static constexpr int NCHUNK = K / KC;         // 128
static constexpr int MT = M / TM;             // 64
static constexpr int NT = N / TN;             // 86
static constexpr int NSTAGE = 4;
static constexpr int ROW_HALFS = KC + 8;      // 40 halves = 80B padded stride
static constexpr int ROW_BYTES = ROW_HALFS * 2;            // 80
static constexpr int TILE_BYTES = TM * ROW_BYTES;          // 10240 (A or B tile)
static constexpr int STAGE_BYTES = 2 * TILE_BYTES;         // 20480
static constexpr int SMEM_BYTES = NSTAGE * STAGE_BYTES;    // 81920
static constexpr int GROUP_M = 16;            // L2 rasterization group

// fp16 scratch (device-global scratch: the sanctioned no-malloc mechanism)
static __device__ __align__(256) __half g_Wh[(size_t)N * K]; // 90.2 MB
static __device__ __align__(256) __half g_Xh[(size_t)M * K]; // 67.1 MB

// ---------------------------------------------------------------------------
// Portable PTX helpers (all compute_80-legal)
// ---------------------------------------------------------------------------
__device__ __forceinline__ uint32_t smem_u32(const void* p) {
    uint32_t a;
    asm("{ .reg .u64 t; cvta.to.shared.u64 t, %1; cvt.u32.u64 %0, t; }"
        : "=r"(a) : "l"(p));
    return a;
}

__device__ __forceinline__ void cp16(uint32_t smem_dst, const void* gsrc) {
    asm volatile("cp.async.cg.shared.global [%0], [%1], 16;"
                 :: "r"(smem_dst), "l"(gsrc));
}

__device__ __forceinline__ void ldmatrix_x4(uint32_t& r0, uint32_t& r1,
                                            uint32_t& r2, uint32_t& r3,
                                            uint32_t addr) {
    asm volatile("ldmatrix.sync.aligned.m8n8.x4.shared.b16 {%0,%1,%2,%3}, [%4];"
                 : "=r"(r0), "=r"(r1), "=r"(r2), "=r"(r3) : "r"(addr));
}

__device__ __forceinline__ void mma_16816(float* c, const uint32_t* a,
                                          const uint32_t* b) {
    asm volatile(
        "mma.sync.aligned.m16n8k16.row.col.f32.f16.f16.f32 "
        "{%0,%1,%2,%3}, {%4,%5,%6,%7}, {%8,%9}, {%0,%1,%2,%3};"
        : "+f"(c[0]), "+f"(c[1]), "+f"(c[2]), "+f"(c[3])
        : "r"(a[0]), "r"(a[1]), "r"(a[2]), "r"(a[3]),
          "r"(b[0]), "r"(b[1]));
}

// ---------------------------------------------------------------------------
// Prepack kernels
// ---------------------------------------------------------------------------
__global__ void conv_w_kernel(const int4* __restrict__ w) {
    size_t idx = (size_t)blockIdx.x * blockDim.x + threadIdx.x;
    size_t total = (size_t)N * K / 4;
    if (idx >= total) return;
    int4 v = w[idx];
    union { __half2 h2[2]; uint2 u2; } cv;
    cv.h2[0] = __halves2half2(__int2half_rn(v.x), __int2half_rn(v.y));
    cv.h2[1] = __halves2half2(__int2half_rn(v.z), __int2half_rn(v.w));
    reinterpret_cast<uint2*>(g_Wh)[idx] = cv.u2;
}

__global__ void conv_x_kernel(const float4* __restrict__ x) {
    size_t idx = (size_t)blockIdx.x * blockDim.x + threadIdx.x;
    size_t total = (size_t)M * K / 4;
    if (idx >= total) return;
    float4 v = x[idx];
    union { __half2 h2[2]; uint2 u2; } cv;
    cv.h2[0] = __floats2half2_rn(v.x, v.y);
    cv.h2[1] = __floats2half2_rn(v.z, v.w);
    reinterpret_cast<uint2*>(g_Xh)[idx] = cv.u2;
}

// ---------------------------------------------------------------------------
// Main GEMM kernel: 256 threads, one 128x128 tile per CTA.
// Warp grid 4(M) x 2(N); warp tile 32(M) x 64(N).
// ---------------------------------------------------------------------------
__global__ __launch_bounds__(256)
void gemm_kernel(const float* __restrict__ scale_ptr, float* __restrict__ out) {
    extern __shared__ __align__(128) char smem[];
    const uint32_t sbase = smem_u32(smem);
    const int tid = threadIdx.x;
    const int wid = tid >> 5;
    const int lane = tid & 31;

    // L2-friendly rasterization: groups of GROUP_M m-tiles across all n-tiles
    int bid = blockIdx.x;
    int g = bid / (GROUP_M * NT);
    int r = bid % (GROUP_M * NT);
    int nt_idx = r / GROUP_M;
    int mt_idx = g * GROUP_M + (r % GROUP_M);
    const int m0 = mt_idx * TM;
    const int n0 = nt_idx * TN;

    // --- cp.async loader mapping: each thread does 2 A + 2 B 16B loads/chunk
    const int ld_row = tid >> 1;              // 0..127
    const int ld_col = (tid & 1) * 32;        // byte offset 0 or 32 within 64B row
    const char* gA = reinterpret_cast<const char*>(g_Xh + (size_t)(m0 + ld_row) * K);
    const char* gB = reinterpret_cast<const char*>(g_Wh + (size_t)(n0 + ld_row) * K);
    const uint32_t sA_row = sbase + (uint32_t)(ld_row * ROW_BYTES + ld_col);
    const uint32_t sB_row = sA_row + (uint32_t)TILE_BYTES;

    auto load_chunk = [&](int c, int s) {
        uint32_t so = (uint32_t)(s * STAGE_BYTES);
        const char* srcA = gA + (size_t)c * (KC * 2) + ld_col;
        const char* srcB = gB + (size_t)c * (KC * 2) + ld_col;
        cp16(sA_row + so,      srcA);
        cp16(sA_row + so + 16, srcA + 16);
        cp16(sB_row + so,      srcB);
        cp16(sB_row + so + 16, srcB + 16);
        asm volatile("cp.async.commit_group;" ::: "memory");
    };

    // --- warp tile coordinates
    const int warp_m = (wid & 3) * 32;        // row offset within CTA tile (A)
    const int warp_n = (wid >> 2) * 64;       // col offset within CTA tile (B)

    // ldmatrix per-lane base offsets (lane&15 -> row, lane>>4 -> 8-half column)
    const uint32_t lm_row = (uint32_t)((lane & 15) * ROW_BYTES);
    const uint32_t lm_col = (uint32_t)((lane >> 4) * 16);
    const uint32_t lmA = sbase + (uint32_t)(warp_m * ROW_BYTES) + lm_row + lm_col;
    const uint32_t lmB = sbase + (uint32_t)TILE_BYTES
                       + (uint32_t)(warp_n * ROW_BYTES) + lm_row + lm_col;

    float acc[2][8][4];
#pragma unroll
    for (int i = 0; i < 2; i++)
#pragma unroll
        for (int j = 0; j < 8; j++)
#pragma unroll
            for (int q = 0; q < 4; q++) acc[i][j][q] = 0.f;

    // Prologue: fill 3 stages
    load_chunk(0, 0);
    load_chunk(1, 1);
    load_chunk(2, 2);

    for (int c = 0; c < NCHUNK; c++) {
        const int s = c & (NSTAGE - 1);
        // ensure chunk c's group has landed
        if (c < NCHUNK - 2)
            asm volatile("cp.async.wait_group 2;" ::: "memory");
        else if (c == NCHUNK - 2)
            asm volatile("cp.async.wait_group 1;" ::: "memory");
        else
            asm volatile("cp.async.wait_group 0;" ::: "memory");
        __syncthreads();

        // issue next load early (stage (c+3)&3 was fully consumed in iter c-1;
        // the barrier above guarantees all warps are past it)
        if (c + 3 < NCHUNK) load_chunk(c + 3, (c + 3) & (NSTAGE - 1));

        const uint32_t so = (uint32_t)(s * STAGE_BYTES);
#pragma unroll
        for (int ks = 0; ks < 2; ks++) {            // two k16 steps per chunk
            uint32_t a[2][4];
#pragma unroll
            for (int mt = 0; mt < 2; mt++)
                ldmatrix_x4(a[mt][0], a[mt][1], a[mt][2], a[mt][3],
                            lmA + so + (uint32_t)(mt * 16 * ROW_BYTES + ks * 32));
            uint32_t b[8][2];
#pragma unroll
            for (int nt2 = 0; nt2 < 4; nt2++) {     // each covers n16 x k16
                uint32_t r0, r1, r2, r3;
                ldmatrix_x4(r0, r1, r2, r3,
                            lmB + so + (uint32_t)(nt2 * 16 * ROW_BYTES + ks * 32));
                b[nt2 * 2 + 0][0] = r0; b[nt2 * 2 + 0][1] = r2;
                b[nt2 * 2 + 1][0] = r1; b[nt2 * 2 + 1][1] = r3;
            }
#pragma unroll
            for (int mt = 0; mt < 2; mt++)
#pragma unroll
                for (int nt = 0; nt < 8; nt++)
                    mma_16816(acc[mt][nt], a[mt], b[nt]);
        }
    }

    // Epilogue: scale + direct gmem stores.
    // mma C frag: lane -> row = lane>>2 (+0/+8), col = (lane&3)*2 (+0/+1)
    const float scl = __ldg(scale_ptr);
    const int er = lane >> 2;
    const int ec = (lane & 3) * 2;
#pragma unroll
    for (int mt = 0; mt < 2; mt++) {
#pragma unroll
        for (int half = 0; half < 2; half++) {
            int m = m0 + warp_m + mt * 16 + half * 8 + er;
            float* orow = out + (size_t)m * N + n0 + warp_n + ec;
#pragma unroll
            for (int nt = 0; nt < 8; nt++) {
                float2 v;
                v.x = acc[mt][nt][half * 2 + 0] * scl;
                v.y = acc[mt][nt][half * 2 + 1] * scl;
                *reinterpret_cast<float2*>(orow + nt * 8) = v;
            }
        }
    }
}

// ---------------------------------------------------------------------------
// Launch
// ---------------------------------------------------------------------------
extern "C" void kernel_launch(void* const* d_in, const int* in_sizes, int n_in,
                              void* d_out, int out_size) {
    const float* x = (const float*)d_in[0];       // [4,2048,4096] fp32
    const int* w = (const int*)d_in[1];           // [11008,4096] int32
    const float* scale = (const float*)d_in[2];   // [1] fp32
    float* out = (float*)d_out;                   // [4,2048,11008] fp32
    (void)in_sizes; (void)n_in; (void)out_size;

    {
        size_t tx = (size_t)M * K / 4;
        size_t tw = (size_t)N * K / 4;
        conv_x_kernel<<<(unsigned)((tx + 255) / 256), 256>>>((const float4*)x);
        conv_w_kernel<<<(unsigned)((tw + 255) / 256), 256>>>((const int4*)w);
    }

    cudaFuncSetAttribute(gemm_kernel,
                         cudaFuncAttributeMaxDynamicSharedMemorySize,
                         SMEM_BYTES);
    gemm_kernel<<<MT * NT, 256, SMEM_BYTES>>>(scale, out);
}

// round 15
// speedup vs baseline: 1.0416x; 1.0416x over previous
#include <cuda_runtime.h>
#include <cuda_fp16.h>
#include <cstdint>

// ============================================================================
// out[m,n] = scale * sum_k x[m,k] * w[n,k]
//   M = 8192, K = 4096, N = 11008; x fp32, w int32 (int8-valued), scale fp32.
//
// Base-sm_103 ptxas target: portable compute_80 ISA only
// (mma.sync m16n8k16 f16->f32, ldmatrix, cp.async).
//
// R11 changes vs R10 (2707 us):
//   - 2 CTAs/SM: __launch_bounds__(256,2), smem 96KB/CTA (was 80KB, 1 CTA)
//   - KC 32->64 (half the __syncthreads), 3 stages, XOR-swizzled 128B rows
//   - one barrier per chunk
// ============================================================================

static constexpr int M = 8192;
static constexpr int N = 11008;
static constexpr int K = 4096;
static constexpr int TM = 128;
static constexpr int TN = 128;
static constexpr int KC = 64;                 // K halves per chunk = 128B row
static constexpr int NCHUNK = K / KC;         // 64
static constexpr int MT = M / TM;             // 64
static constexpr int NT = N / TN;             // 86
static constexpr int NSTAGE = 3;
static constexpr int ROW_BYTES = KC * 2;                   // 128
static constexpr int TILE_BYTES = TM * ROW_BYTES;          // 16384
static constexpr int STAGE_BYTES = 2 * TILE_BYTES;         // 32768
static constexpr int SMEM_BYTES = NSTAGE * STAGE_BYTES;    // 98304 (x2 CTAs = 192KB)
static constexpr int GROUP_M = 16;            // L2 rasterization group

// fp16 scratch (device-global scratch: the sanctioned no-malloc mechanism)
static __device__ __align__(256) __half g_Wh[(size_t)N * K]; // 90.2 MB
static __device__ __align__(256) __half g_Xh[(size_t)M * K]; // 67.1 MB

// ---------------------------------------------------------------------------
// Portable PTX helpers (all compute_80-legal)
// ---------------------------------------------------------------------------
__device__ __forceinline__ uint32_t smem_u32(const void* p) {
    uint32_t a;
    asm("{ .reg .u64 t; cvta.to.shared.u64 t, %1; cvt.u32.u64 %0, t; }"
        : "=r"(a) : "l"(p));
    return a;
}

__device__ __forceinline__ void cp16(uint32_t smem_dst, const void* gsrc) {
    asm volatile("cp.async.cg.shared.global [%0], [%1], 16;"
                 :: "r"(smem_dst), "l"(gsrc));
}

__device__ __forceinline__ void ldmatrix_x4(uint32_t& r0, uint32_t& r1,
                                            uint32_t& r2, uint32_t& r3,
                                            uint32_t addr) {
    asm volatile("ldmatrix.sync.aligned.m8n8.x4.shared.b16 {%0,%1,%2,%3}, [%4];"
                 : "=r"(r0), "=r"(r1), "=r"(r2), "=r"(r3) : "r"(addr));
}

__device__ __forceinline__ void mma_16816(float* c, const uint32_t* a,
                                          const uint32_t* b) {
    asm volatile(
        "mma.sync.aligned.m16n8k16.row.col.f32.f16.f16.f32 "
        "{%0,%1,%2,%3}, {%4,%5,%6,%7}, {%8,%9}, {%0,%1,%2,%3};"
        : "+f"(c[0]), "+f"(c[1]), "+f"(c[2]), "+f"(c[3])
        : "r"(a[0]), "r"(a[1]), "r"(a[2]), "r"(a[3]),
          "r"(b[0]), "r"(b[1]));
}

// ---------------------------------------------------------------------------
// Prepack kernels
// ---------------------------------------------------------------------------
__global__ void conv_w_kernel(const int4* __restrict__ w) {
    size_t idx = (size_t)blockIdx.x * blockDim.x + threadIdx.x;
    size_t total = (size_t)N * K / 4;
    if (idx >= total) return;
    int4 v = w[idx];
    union { __half2 h2[2]; uint2 u2; } cv;
    cv.h2[0] = __halves2half2(__int2half_rn(v.x), __int2half_rn(v.y));
    cv.h2[1] = __halves2half2(__int2half_rn(v.z), __int2half_rn(v.w));
    reinterpret_cast<uint2*>(g_Wh)[idx] = cv.u2;
}

__global__ void conv_x_kernel(const float4* __restrict__ x) {
    size_t idx = (size_t)blockIdx.x * blockDim.x + threadIdx.x;
    size_t total = (size_t)M * K / 4;
    if (idx >= total) return;
    float4 v = x[idx];
    union { __half2 h2[2]; uint2 u2; } cv;
    cv.h2[0] = __floats2half2_rn(v.x, v.y);
    cv.h2[1] = __floats2half2_rn(v.z, v.w);
    reinterpret_cast<uint2*>(g_Xh)[idx] = cv.u2;
}

// ---------------------------------------------------------------------------
// Main GEMM kernel: 256 threads, one 128x128 tile per CTA, 2 CTAs/SM.
// Warp grid 4(M) x 2(N); warp tile 32(M) x 64(N).
// Smem layout: per stage [A tile 128x128B][B tile 128x128B], XOR-swizzled:
//   byte (row, col) stored at row*128 + (col ^ ((row & 7) << 4)).
// ---------------------------------------------------------------------------
__global__ __launch_bounds__(256, 2)
void gemm_kernel(const float* __restrict__ scale_ptr, float* __restrict__ out) {
    extern __shared__ __align__(1024) char smem[];
    const uint32_t sbase = smem_u32(smem);
    const int tid = threadIdx.x;
    const int wid = tid >> 5;
    const int lane = tid & 31;

    // L2-friendly rasterization: groups of GROUP_M m-tiles across all n-tiles
    int bid = blockIdx.x;
    int g = bid / (GROUP_M * NT);
    int r = bid % (GROUP_M * NT);
    int nt_idx = r / GROUP_M;
    int mt_idx = g * GROUP_M + (r % GROUP_M);
    const int m0 = mt_idx * TM;
    const int n0 = nt_idx * TN;

    const float scl = __ldg(scale_ptr);

    // --- cp.async loader: 2 threads per row, 64B (4x16B) each, A + B
    const int ld_row = tid >> 1;               // 0..127
    const int ld_col = (tid & 1) * 64;         // 0 or 64 within 128B row
    const char* gA = reinterpret_cast<const char*>(g_Xh + (size_t)(m0 + ld_row) * K);
    const char* gB = reinterpret_cast<const char*>(g_Wh + (size_t)(n0 + ld_row) * K);
    const uint32_t ld_xor = (uint32_t)((ld_row & 7) << 4);
    const uint32_t sA_row = sbase + (uint32_t)(ld_row * ROW_BYTES);
    const uint32_t sB_row = sA_row + (uint32_t)TILE_BYTES;

    auto load_chunk = [&](int c, int s) {
        const uint32_t so = (uint32_t)(s * STAGE_BYTES);
        const char* srcA = gA + (size_t)c * ROW_BYTES + ld_col;
        const char* srcB = gB + (size_t)c * ROW_BYTES + ld_col;
#pragma unroll
        for (int j = 0; j < 4; j++) {
            uint32_t sw = ((uint32_t)(ld_col + j * 16)) ^ ld_xor;
            cp16(sA_row + so + sw, srcA + j * 16);
            cp16(sB_row + so + sw, srcB + j * 16);
        }
        asm volatile("cp.async.commit_group;" ::: "memory");
    };

    // --- warp tile coordinates
    const int warp_m = (wid & 3) * 32;
    const int warp_n = (wid >> 2) * 64;

    // ldmatrix per-lane addressing (swizzled):
    //   lanes 0-15 -> rows 0-15 col chunk 0; lanes 16-31 -> rows 0-15 chunk +16B
    const uint32_t lrow = (uint32_t)(lane & 15);
    const uint32_t lxor = (uint32_t)((lane & 7) << 4);
    const uint32_t cbase = (uint32_t)((lane >> 4) * 16);
    const uint32_t aA = sbase + (uint32_t)((warp_m + (int)lrow) * ROW_BYTES);
    const uint32_t aB = sbase + (uint32_t)TILE_BYTES
                      + (uint32_t)((warp_n + (int)lrow) * ROW_BYTES);

    float acc[2][8][4];
#pragma unroll
    for (int i = 0; i < 2; i++)
#pragma unroll
        for (int j = 0; j < 8; j++)
#pragma unroll
            for (int q = 0; q < 4; q++) acc[i][j][q] = 0.f;

    // Prologue: fill 2 of 3 stages
    load_chunk(0, 0);
    load_chunk(1, 1);

    int s = 0;       // stage holding chunk c
    int s2 = 2;      // stage to load chunk c+2 into
    for (int c = 0; c < NCHUNK; c++) {
        // chunk c landed when at most 1 newer group is pending
        if (c < NCHUNK - 1)
            asm volatile("cp.async.wait_group 1;" ::: "memory");
        else
            asm volatile("cp.async.wait_group 0;" ::: "memory");
        __syncthreads();   // also fences prior iter's reads of stage s2

        if (c + 2 < NCHUNK) load_chunk(c + 2, s2);

        const uint32_t so = (uint32_t)(s * STAGE_BYTES);
#pragma unroll
        for (int ks = 0; ks < 4; ks++) {           // four k16 steps per chunk
            const uint32_t csw = ((uint32_t)(ks * 32) + cbase) ^ lxor;
            uint32_t a[2][4];
#pragma unroll
            for (int mt = 0; mt < 2; mt++)
                ldmatrix_x4(a[mt][0], a[mt][1], a[mt][2], a[mt][3],
                            aA + so + (uint32_t)(mt * 16 * ROW_BYTES) + csw);
            uint32_t b[8][2];
#pragma unroll
            for (int nt2 = 0; nt2 < 4; nt2++) {    // each covers n16 x k16
                uint32_t r0, r1, r2, r3;
                ldmatrix_x4(r0, r1, r2, r3,
                            aB + so + (uint32_t)(nt2 * 16 * ROW_BYTES) + csw);
                b[nt2 * 2 + 0][0] = r0; b[nt2 * 2 + 0][1] = r2;
                b[nt2 * 2 + 1][0] = r1; b[nt2 * 2 + 1][1] = r3;
            }
#pragma unroll
            for (int mt = 0; mt < 2; mt++)
#pragma unroll
                for (int nt = 0; nt < 8; nt++)
                    mma_16816(acc[mt][nt], a[mt], b[nt]);
        }

        // rotate stages: s -> s+1, s2 -> s2+1 (mod 3)
        s = (s == 2) ? 0 : s + 1;
        s2 = (s2 == 2) ? 0 : s2 + 1;
    }

    // Epilogue: scale + direct gmem stores.
    // mma C frag: row = lane>>2 (+0/+8), col = (lane&3)*2 (+0/+1)
    const int er = lane >> 2;
    const int ec = (lane & 3) * 2;
#pragma unroll
    for (int mt = 0; mt < 2; mt++) {
#pragma unroll
        for (int half = 0; half < 2; half++) {
            int m = m0 + warp_m + mt * 16 + half * 8 + er;
            float* orow = out + (size_t)m * N + n0 + warp_n + ec;
#pragma unroll
            for (int nt = 0; nt < 8; nt++) {
                float2 v;
                v.x = acc[mt][nt][half * 2 + 0] * scl;
                v.y = acc[mt][nt][half * 2 + 1] * scl;
                *reinterpret_cast<float2*>(orow + nt * 8) = v;
            }
        }
    }
}

// ---------------------------------------------------------------------------
// Launch
// ---------------------------------------------------------------------------
extern "C" void kernel_launch(void* const* d_in, const int* in_sizes, int n_in,
                              void* d_out, int out_size) {
    const float* x = (const float*)d_in[0];       // [4,2048,4096] fp32
    const int* w = (const int*)d_in[1];           // [11008,4096] int32
    const float* scale = (const float*)d_in[2];   // [1] fp32
    float* out = (float*)d_out;                   // [4,2048,11008] fp32
    (void)in_sizes; (void)n_in; (void)out_size;

    {
        size_t tx = (size_t)M * K / 4;
        size_t tw = (size_t)N * K / 4;
        conv_x_kernel<<<(unsigned)((tx + 255) / 256), 256>>>((const float4*)x);
        conv_w_kernel<<<(unsigned)((tw + 255) / 256), 256>>>((const int4*)w);
    }

    cudaFuncSetAttribute(gemm_kernel,
                         cudaFuncAttributeMaxDynamicSharedMemorySize,
                         SMEM_BYTES);
    gemm_kernel<<<MT * NT, 256, SMEM_BYTES>>>(scale, out);
}